// round 8
// baseline (speedup 1.0000x reference)
#include <cuda_runtime.h>
#include <math.h>

// YearOperatorRouter: per-sample routed 3x3 edge magnitude.
// kx = [[-p,0,p],[-q,0,q],[-p,0,p]], ky = kx^T; out = sqrt(gx^2+gy^2+eps)*s, zero pad.
//
// R8: R7 skeleton + packed f32x2 math (Blackwell FFMA2/FADD2 — only reachable
// via PTX). Window rows held as 3 packed pairs; vertical sum/diff rows and all
// gx/gy/g2 FMAs run 2 pixels per issue. Horizontal +-1 taps are whole-pair
// shifts (no repack); only the gy center tap needs 2 cross-pair repacks/row.

#define W 256
#define H 256
#define RPT 8   // output rows per thread

typedef unsigned long long ull;

#define PACKF2(o, lo, hi)  asm("mov.b64 %0, {%1, %2};" : "=l"(o) : "f"(lo), "f"(hi))
#define UNPACKF2(lo, hi, in) asm("mov.b64 {%0, %1}, %2;" : "=f"(lo), "=f"(hi) : "l"(in))
#define ADDX2(o, a, b)     asm("add.rn.f32x2 %0, %1, %2;" : "=l"(o) : "l"(a), "l"(b))
#define SUBX2(o, a, b)     asm("sub.rn.f32x2 %0, %1, %2;" : "=l"(o) : "l"(a), "l"(b))
#define MULX2(o, a, b)     asm("mul.rn.f32x2 %0, %1, %2;" : "=l"(o) : "l"(a), "l"(b))
#define FMAX2(o, a, b, c)  asm("fma.rn.f32x2 %0, %1, %2, %3;" : "=l"(o) : "l"(a), "l"(b), "l"(c))

// Window w[0..5] at x0-1..x0+4 as pairs P[0]=(w0,w1) P[1]=(w2,w3) P[2]=(w4,w5).
__device__ __forceinline__ void load_rowP(const float* __restrict__ row, int x0,
                                          bool hasL, bool hasR, ull P[3]) {
    float4 m = __ldg(reinterpret_cast<const float4*>(row + x0));
    float L = hasL ? __ldg(row + x0 - 1) : 0.0f;
    float R = hasR ? __ldg(row + x0 + 4) : 0.0f;
    PACKF2(P[0], L,   m.x);
    PACKF2(P[1], m.y, m.z);
    PACKF2(P[2], m.w, R);
}

__global__ __launch_bounds__(128)
void year_router_kernel(const float* __restrict__ x,
                        const float* __restrict__ alpha,
                        const float* __restrict__ scale,
                        const int*   __restrict__ year,
                        float* __restrict__ out,
                        int C)
{
    const int x0 = threadIdx.x * 4;                          // 0..252 (blockDim.x = 64)
    const int y0 = (blockIdx.y * 2 + threadIdx.y) * RPT;     // blockDim.y = 2
    const int bc = blockIdx.z;
    const int b  = bc / C;

    // ---- per-sample operator parameters (uniform per z-block), s folded in ----
    const int yr = __ldg(year + b);
    float p, q, eps;
    if (yr == 2019) {            // sobel
        p = 1.0f; q = 2.0f; eps = 1e-8f;
    } else if (yr == 2020) {     // scharr
        p = 3.0f; q = 10.0f; eps = 1e-8f;
    } else {                     // learnable: sigmoid mix / max|k| (= q term), s folded
        float a  = 1.0f / (1.0f + expf(-__ldg(alpha)));
        float pm = 3.0f  - 2.0f * a;
        float qm = 10.0f - 8.0f * a;            // qm > pm > 0 for a in (0,1)
        float s  = 1.0f / (1.0f + expf(-__ldg(scale)));
        p = (pm / qm) * s;
        q = s;
        eps = 1e-6f * s * s;
    }
    ull pp, qq, ee;
    PACKF2(pp, p, p);
    PACKF2(qq, q, q);
    PACKF2(ee, eps, eps);

    const bool hasL = (x0 > 0);
    const bool hasR = (x0 + 4 < W);

    const float* __restrict__ base  = x   + (size_t)bc * H * W;
    float*       __restrict__ obase = out + (size_t)bc * H * W;

    // ---- rolling 3-row packed window ----
    ull rows[3][3];
    if (y0 > 0) load_rowP(base + (size_t)(y0 - 1) * W, x0, hasL, hasR, rows[0]);
    else        { rows[0][0] = rows[0][1] = rows[0][2] = 0ull; }
    load_rowP(base + (size_t)y0 * W, x0, hasL, hasR, rows[1]);

#pragma unroll
    for (int i = 0; i < RPT; i++) {
        const int yn = y0 + i + 1;
        ull* Cr = rows[(i + 2) % 3];
        if (yn < H) load_rowP(base + (size_t)yn * W, x0, hasL, hasR, Cr);
        else        { Cr[0] = Cr[1] = Cr[2] = 0ull; }

        const ull* Ar = rows[(i + 0) % 3];   // y-1
        const ull* Br = rows[(i + 1) % 3];   // y

        // vertical sum/diff rows (element-wise, packed)
        ull d0, d1, d2, t0, t1, t2;
        SUBX2(d0, Cr[0], Ar[0]);  SUBX2(d1, Cr[1], Ar[1]);  SUBX2(d2, Cr[2], Ar[2]);
        ADDX2(t0, Cr[0], Ar[0]);  ADDX2(t1, Cr[1], Ar[1]);  ADDX2(t2, Cr[2], Ar[2]);

        // gx = q*(B[j+2]-B[j]) + p*(t[j+2]-t[j])  — +-2 taps are whole-pair shifts
        ull ht0, ht1, hb0, hb1, gx01, gx23, tmp;
        SUBX2(ht0, t1, t0);       SUBX2(ht1, t2, t1);
        SUBX2(hb0, Br[1], Br[0]); SUBX2(hb1, Br[2], Br[1]);
        MULX2(tmp, pp, ht0);      FMAX2(gx01, qq, hb0, tmp);
        MULX2(tmp, pp, ht1);      FMAX2(gx23, qq, hb1, tmp);

        // gy = q*d[j+1] + p*(d[j]+d[j+2]) — center tap needs 2 cross-pair packs
        ull sd0, sd1;
        ADDX2(sd0, d0, d1);       ADDX2(sd1, d1, d2);
        float d0l, d0h, d1l, d1h, d2l, d2h;
        UNPACKF2(d0l, d0h, d0); UNPACKF2(d1l, d1h, d1); UNPACKF2(d2l, d2h, d2);
        ull dm0, dm1;
        PACKF2(dm0, d0h, d1l);    PACKF2(dm1, d1h, d2l);
        ull gy01, gy23;
        MULX2(tmp, pp, sd0);      FMAX2(gy01, qq, dm0, tmp);
        MULX2(tmp, pp, sd1);      FMAX2(gy23, qq, dm1, tmp);

        // g2 = gx^2 + gy^2 + eps
        ull g01, g23;
        FMAX2(g01, gy01, gy01, ee);  FMAX2(g01, gx01, gx01, g01);
        FMAX2(g23, gy23, gy23, ee);  FMAX2(g23, gx23, gx23, g23);

        float g0, g1, g2v, g3;
        UNPACKF2(g0, g1, g01);  UNPACKF2(g2v, g3, g23);
        float o0 = g0  * __frsqrt_rn(g0);
        float o1 = g1  * __frsqrt_rn(g1);
        float o2 = g2v * __frsqrt_rn(g2v);
        float o3 = g3  * __frsqrt_rn(g3);

        *reinterpret_cast<float4*>(obase + (size_t)(y0 + i) * W + x0) =
            make_float4(o0, o1, o2, o3);
    }
}

extern "C" void kernel_launch(void* const* d_in, const int* in_sizes, int n_in,
                              void* d_out, int out_size)
{
    const float* x     = (const float*)d_in[0];   // [B, C, 256, 256] f32
    const float* alpha = (const float*)d_in[1];   // scalar f32
    const float* scale = (const float*)d_in[2];   // [1] f32
    const int*   year  = (const int*)d_in[3];     // [B] int32
    float* out = (float*)d_out;

    const int B  = in_sizes[3];
    const int BC = in_sizes[0] / (H * W);
    const int C  = BC / B;

    dim3 block(64, 2, 1);                 // 128 threads: 64 x-tiles, 2 row-strips
    dim3 grid(1, H / (RPT * 2), BC);      // (1, 16, 288) = 4608 blocks

    year_router_kernel<<<grid, block>>>(x, alpha, scale, year, out, C);
}

// round 9
// speedup vs baseline: 1.0653x; 1.0653x over previous
#include <cuda_runtime.h>
#include <math.h>

// YearOperatorRouter: per-sample routed 3x3 edge magnitude.
// kx = [[-p,0,p],[-q,0,q],[-p,0,p]], ky = kx^T; out = sqrt(gx^2+gy^2+eps)*s, zero pad.
//
// R9: R7 math kernel (register rolling window, rsqrt, s folded into p/q/eps)
// reshaped for the scheduler:
//   - persistent grid-stride loop, grid = 148 SMs x 12 resident blocks -> one
//     full wave, no wave-quantization tail
//   - __stcs streaming stores keep the input L2-resident
//   - lean register set (no t[] row) to hold 12 blocks/SM

#define W 256
#define H 256
#define RPT 8                 // output rows per thread
#define TILE_ROWS 16          // rows per tile (blockDim.y = 2 strips of RPT)
#define TILES_PER_IMG (H / TILE_ROWS)   // 16
#define NUM_SMS 148
#define BLOCKS_PER_SM 12

__device__ __forceinline__ void load_row6(const float* __restrict__ row, int x0,
                                          bool hasL, bool hasR, float r[6]) {
    float4 m = __ldg(reinterpret_cast<const float4*>(row + x0));
    r[0] = hasL ? __ldg(row + x0 - 1) : 0.0f;
    r[1] = m.x; r[2] = m.y; r[3] = m.z; r[4] = m.w;
    r[5] = hasR ? __ldg(row + x0 + 4) : 0.0f;
}

__device__ __forceinline__ void zero_row6(float r[6]) {
#pragma unroll
    for (int j = 0; j < 6; j++) r[j] = 0.0f;
}

__global__ __launch_bounds__(128, BLOCKS_PER_SM)
void year_router_kernel(const float* __restrict__ x,
                        const float* __restrict__ alpha,
                        const float* __restrict__ scale,
                        const int*   __restrict__ year,
                        float* __restrict__ out,
                        int C, int n_tiles)
{
    const int x0   = threadIdx.x * 4;          // 0..252 (blockDim.x = 64)
    const bool hasL = (x0 > 0);
    const bool hasR = (x0 + 4 < W);

    for (int t = blockIdx.x; t < n_tiles; t += gridDim.x) {
        const int bc = t / TILES_PER_IMG;
        const int ys = t - bc * TILES_PER_IMG;
        const int y0 = ys * TILE_ROWS + threadIdx.y * RPT;

        // ---- per-sample operator parameters (uniform per tile), s folded ----
        const int yr = __ldg(year + bc / C);
        float p, q, eps;
        if (yr == 2019) {            // sobel
            p = 1.0f; q = 2.0f; eps = 1e-8f;
        } else if (yr == 2020) {     // scharr
            p = 3.0f; q = 10.0f; eps = 1e-8f;
        } else {                     // learnable: sigmoid mix / max|k| (= q term)
            float a  = 1.0f / (1.0f + expf(-__ldg(alpha)));
            float pm = 3.0f  - 2.0f * a;
            float qm = 10.0f - 8.0f * a;        // qm > pm > 0 for a in (0,1)
            float s  = 1.0f / (1.0f + expf(-__ldg(scale)));
            p = (pm / qm) * s;
            q = s;
            eps = 1e-6f * s * s;
        }

        const float* __restrict__ base  = x   + (size_t)bc * (H * W);
        float*       __restrict__ obase = out + (size_t)bc * (H * W) + (size_t)y0 * W + x0;

        // ---- rolling 3-row register window ----
        float rows[3][6];
        if (y0 > 0) load_row6(base + (size_t)(y0 - 1) * W, x0, hasL, hasR, rows[0]);
        else        zero_row6(rows[0]);
        load_row6(base + (size_t)y0 * W, x0, hasL, hasR, rows[1]);

#pragma unroll
        for (int i = 0; i < RPT; i++) {
            const int yn = y0 + i + 1;
            float* rn = rows[(i + 2) % 3];
            if (yn < H) load_row6(base + (size_t)yn * W, x0, hasL, hasR, rn);
            else        zero_row6(rn);

            const float* r0 = rows[(i + 0) % 3];   // y-1
            const float* r1 = rows[(i + 1) % 3];   // y
            const float* r2 = rn;                  // y+1

            // vertical diffs (shared across adjacent outputs)
            float d[6];
#pragma unroll
            for (int j = 0; j < 6; j++) d[j] = r2[j] - r0[j];

            float o[4];
#pragma unroll
            for (int j = 0; j < 4; j++) {
                float gx = fmaf(q, r1[j + 2] - r1[j],
                                p * ((r0[j + 2] - r0[j]) + (r2[j + 2] - r2[j])));
                float gy = fmaf(q, d[j + 1], p * (d[j] + d[j + 2]));
                float g2 = fmaf(gx, gx, fmaf(gy, gy, eps));
                o[j] = g2 * __frsqrt_rn(g2);       // sqrt(g2), g2 >= eps > 0
            }
            __stcs(reinterpret_cast<float4*>(obase + (size_t)i * W),
                   make_float4(o[0], o[1], o[2], o[3]));
        }
    }
}

extern "C" void kernel_launch(void* const* d_in, const int* in_sizes, int n_in,
                              void* d_out, int out_size)
{
    const float* x     = (const float*)d_in[0];   // [B, C, 256, 256] f32
    const float* alpha = (const float*)d_in[1];   // scalar f32
    const float* scale = (const float*)d_in[2];   // [1] f32
    const int*   year  = (const int*)d_in[3];     // [B] int32
    float* out = (float*)d_out;

    const int B  = in_sizes[3];
    const int BC = in_sizes[0] / (H * W);
    const int C  = BC / B;
    const int n_tiles = BC * TILES_PER_IMG;       // 288 * 16 = 4608

    dim3 block(64, 2, 1);                         // 128 threads
    int grid = NUM_SMS * BLOCKS_PER_SM;           // 1776 = one full resident wave
    if (grid > n_tiles) grid = n_tiles;

    year_router_kernel<<<grid, block>>>(x, alpha, scale, year, out, C, n_tiles);
}